// round 1
// baseline (speedup 1.0000x reference)
#include <cuda_runtime.h>
#include <math.h>

#define BB 8
#define SS 2000
#define MM (BB*SS)          // 16000 rows
#define DD 256
#define HH 2
#define HDIM 128
#define FFN 256
#define WIN 99

// ---------------- scratch (device globals; no allocation allowed) ----------
__device__ float g_x   [MM*DD];   // encoder out + pos
__device__ float g_qkv [MM*3*DD]; // packed qkv
__device__ float g_ctx [MM*DD];   // attention context
__device__ float g_att [MM*DD];   // out_proj output
__device__ float g_h1  [MM*DD];   // after LN1
__device__ float g_ff  [MM*FFN];  // relu(ffn1)
__device__ float g_ff2 [MM*DD];   // ffn2
__device__ float g_h2  [MM*DD];   // after LN2
__device__ float g_t   [MM*64];   // fc1 out

// ---------------- generic fp32 GEMM: C[m,n] = sum_k A[m,k]*B[n,k] + bias[n] -
// A: [M,K] row-major, B: [N,K] row-major (torch Linear weight layout).
// TM=128, TK=16, TN template (128 or 64). 256 threads, micro-tile 8 x (TN/16).
// EPI: 0 = bias only, 1 = bias + positional encoding, 2 = bias + relu.
#define TM 128
#define TK 16

template<int TN, int EPI>
__global__ void __launch_bounds__(256, 2)
sgemm_kernel(const float* __restrict__ A, const float* __restrict__ B,
             const float* __restrict__ bias, float* __restrict__ C,
             int K, int N)
{
    __shared__ float As[TK][TM + 4];
    __shared__ float Bs[TK][TN + 4];

    const int tid = threadIdx.x;
    const int tx  = tid & 15;          // 0..15 (cols)
    const int ty  = tid >> 4;          // 0..15 (rows)
    const int row0 = blockIdx.x * TM;
    const int col0 = blockIdx.y * TN;
    constexpr int W = TN / 16;         // 8 or 4 cols per thread

    float acc[8][W];
#pragma unroll
    for (int i = 0; i < 8; i++)
#pragma unroll
        for (int j = 0; j < W; j++) acc[i][j] = 0.f;

    const int lr = tid >> 2;           // 0..63
    const int lk = (tid & 3) * 4;      // 0,4,8,12

    for (int k0 = 0; k0 < K; k0 += TK) {
        // load A tile 128x16, store transposed
#pragma unroll
        for (int rr = 0; rr < TM; rr += 64) {
            float4 a = *(const float4*)(A + (size_t)(row0 + lr + rr) * K + k0 + lk);
            As[lk+0][lr+rr] = a.x; As[lk+1][lr+rr] = a.y;
            As[lk+2][lr+rr] = a.z; As[lk+3][lr+rr] = a.w;
        }
        // load B tile TNx16, store transposed
#pragma unroll
        for (int rr = 0; rr < TN; rr += 64) {
            float4 b = *(const float4*)(B + (size_t)(col0 + lr + rr) * K + k0 + lk);
            Bs[lk+0][lr+rr] = b.x; Bs[lk+1][lr+rr] = b.y;
            Bs[lk+2][lr+rr] = b.z; Bs[lk+3][lr+rr] = b.w;
        }
        __syncthreads();

#pragma unroll
        for (int k = 0; k < TK; k++) {
            float a[8], b[W];
            *(float4*)&a[0] = *(const float4*)&As[k][ty * 8];
            *(float4*)&a[4] = *(const float4*)&As[k][ty * 8 + 4];
            *(float4*)&b[0] = *(const float4*)&Bs[k][tx * W];
            if (W == 8) *(float4*)&b[4] = *(const float4*)&Bs[k][tx * W + 4];
#pragma unroll
            for (int i = 0; i < 8; i++)
#pragma unroll
                for (int j = 0; j < W; j++)
                    acc[i][j] += a[i] * b[j];
        }
        __syncthreads();
    }

    // epilogue
#pragma unroll
    for (int i = 0; i < 8; i++) {
        const int r = row0 + ty * 8 + i;
#pragma unroll
        for (int j = 0; j < W; j++) {
            const int c = col0 + tx * W + j;
            float v = acc[i][j] + bias[c];
            if (EPI == 2) v = fmaxf(v, 0.f);
            if (EPI == 1) {
                const int s = r % SS;
                const int p = c >> 1;
                // div = exp(-(2p) * ln(10000)/256)
                const float div = expf(-(float)(2 * p) * 0.03597789207803197f);
                const float ang = (float)s * div;
                v += (c & 1) ? cosf(ang) : sinf(ang);
            }
            C[(size_t)r * N + c] = v;
        }
    }
}

// ---------------- banded attention: warp per query --------------------------
__global__ void __launch_bounds__(256)
attn_kernel(const float* __restrict__ qkv, float* __restrict__ ctx)
{
    const int w    = threadIdx.x >> 5;
    const int lane = threadIdx.x & 31;
    const int qb   = blockIdx.x;            // 0 .. B*H*(S/8)-1
    const int bh   = qb / (SS / 8);
    const int i    = (qb % (SS / 8)) * 8 + w;
    const int b    = bh >> 1;
    const int h    = bh & 1;

    const float* base = qkv + (size_t)b * SS * (3 * DD);
    const float4 qv = ((const float4*)(base + (size_t)i * (3 * DD) + h * HDIM))[lane];

    const int jstart = (i > WIN) ? (i - WIN) : 0;
    const int cnt    = i - jstart + 1;      // <= 100

    __shared__ float sc[8][104];

    // pass 1: scores + running max (all lanes end up with full dot via butterfly)
    float mx = -1e30f;
    const float* krow = base + (size_t)jstart * (3 * DD) + DD + h * HDIM;
    for (int jj = 0; jj < cnt; jj++) {
        float4 kv = ((const float4*)(krow + (size_t)jj * (3 * DD)))[lane];
        float p = qv.x * kv.x + qv.y * kv.y + qv.z * kv.z + qv.w * kv.w;
#pragma unroll
        for (int o = 16; o; o >>= 1) p += __shfl_xor_sync(0xffffffffu, p, o);
        p *= 0.08838834764831845f;           // 1/sqrt(128)
        mx = fmaxf(mx, p);
        if (lane == 0) sc[w][jj] = p;
    }
    __syncwarp();

    // pass 2: exp + sum
    float se = 0.f;
    for (int jj = lane; jj < cnt; jj += 32) {
        float e = expf(sc[w][jj] - mx);
        sc[w][jj] = e;
        se += e;
    }
    __syncwarp();
#pragma unroll
    for (int o = 16; o; o >>= 1) se += __shfl_xor_sync(0xffffffffu, se, o);

    // pass 3: weighted V accumulation
    float4 acc = make_float4(0.f, 0.f, 0.f, 0.f);
    const float* vrow = base + (size_t)jstart * (3 * DD) + 2 * DD + h * HDIM;
    for (int jj = 0; jj < cnt; jj++) {
        const float p = sc[w][jj];
        float4 vv = ((const float4*)(vrow + (size_t)jj * (3 * DD)))[lane];
        acc.x += p * vv.x; acc.y += p * vv.y;
        acc.z += p * vv.z; acc.w += p * vv.w;
    }
    const float inv = 1.f / se;
    ((float4*)(ctx + ((size_t)(b * SS + i)) * DD + h * HDIM))[lane] =
        make_float4(acc.x * inv, acc.y * inv, acc.z * inv, acc.w * inv);
}

// ---------------- residual add + layernorm (row per block, 256 threads) -----
__global__ void __launch_bounds__(256)
add_ln_kernel(const float* __restrict__ x, const float* __restrict__ y,
              const float* __restrict__ w, const float* __restrict__ b,
              float* __restrict__ out)
{
    const int row = blockIdx.x;
    const int t   = threadIdx.x;
    const size_t idx = (size_t)row * DD + t;
    const float v = x[idx] + y[idx];

    __shared__ float s1[8], s2[8];
    float r = v;
#pragma unroll
    for (int o = 16; o; o >>= 1) r += __shfl_xor_sync(0xffffffffu, r, o);
    if ((t & 31) == 0) s1[t >> 5] = r;
    __syncthreads();
    float tot = s1[0] + s1[1] + s1[2] + s1[3] + s1[4] + s1[5] + s1[6] + s1[7];
    const float mean = tot * (1.f / DD);

    const float d = v - mean;
    float q = d * d;
#pragma unroll
    for (int o = 16; o; o >>= 1) q += __shfl_xor_sync(0xffffffffu, q, o);
    if ((t & 31) == 0) s2[t >> 5] = q;
    __syncthreads();
    float tot2 = s2[0] + s2[1] + s2[2] + s2[3] + s2[4] + s2[5] + s2[6] + s2[7];
    const float var = tot2 * (1.f / DD);
    const float inv = 1.f / sqrtf(var + 1e-5f);

    out[idx] = d * inv * w[t] + b[t];
}

// ---------------- fc2: warp per row, dot over 64 ----------------------------
__global__ void __launch_bounds__(256)
fc2_kernel(const float* __restrict__ t64, const float* __restrict__ w,
           const float* __restrict__ bptr, float* __restrict__ out)
{
    const int warp = (blockIdx.x * blockDim.x + threadIdx.x) >> 5;
    const int lane = threadIdx.x & 31;
    if (warp >= MM) return;
    float s = t64[(size_t)warp * 64 + lane] * w[lane]
            + t64[(size_t)warp * 64 + lane + 32] * w[lane + 32];
#pragma unroll
    for (int o = 16; o; o >>= 1) s += __shfl_xor_sync(0xffffffffu, s, o);
    if (lane == 0) out[warp] = s + bptr[0];
}

// ---------------- host launch ------------------------------------------------
static float* dptr(const void* sym) {
    void* p = nullptr;
    cudaGetSymbolAddress(&p, sym);
    return (float*)p;
}

extern "C" void kernel_launch(void* const* d_in, const int* in_sizes, int n_in,
                              void* d_out, int out_size)
{
    const float* src        = (const float*)d_in[0];
    // d_in[1] = input_lengths (int64) — unused by the reference math
    const float* W_enc      = (const float*)d_in[2];
    const float* b_enc      = (const float*)d_in[3];
    const float* in_proj_w  = (const float*)d_in[4];
    const float* in_proj_b  = (const float*)d_in[5];
    const float* out_proj_w = (const float*)d_in[6];
    const float* out_proj_b = (const float*)d_in[7];
    const float* ln1_w      = (const float*)d_in[8];
    const float* ln1_b      = (const float*)d_in[9];
    const float* lin1_w     = (const float*)d_in[10];
    const float* lin1_b     = (const float*)d_in[11];
    const float* lin2_w     = (const float*)d_in[12];
    const float* lin2_b     = (const float*)d_in[13];
    const float* ln2_w      = (const float*)d_in[14];
    const float* ln2_b      = (const float*)d_in[15];
    const float* fc1_w      = (const float*)d_in[16];
    const float* fc1_b      = (const float*)d_in[17];
    const float* fc2_w      = (const float*)d_in[18];
    const float* fc2_b      = (const float*)d_in[19];
    float* out = (float*)d_out;

    float* x   = dptr(g_x);
    float* qkv = dptr(g_qkv);
    float* ctx = dptr(g_ctx);
    float* att = dptr(g_att);
    float* h1  = dptr(g_h1);
    float* ff  = dptr(g_ff);
    float* ff2 = dptr(g_ff2);
    float* h2  = dptr(g_h2);
    float* t64 = dptr(g_t);

    const dim3 blk(256);

    // 1. encoder projection + positional encoding
    sgemm_kernel<128, 1><<<dim3(MM / TM, DD / 128), blk>>>(src, W_enc, b_enc, x, DD, DD);
    // 2. qkv projection
    sgemm_kernel<128, 0><<<dim3(MM / TM, (3 * DD) / 128), blk>>>(x, in_proj_w, in_proj_b, qkv, DD, 3 * DD);
    // 3. banded attention
    attn_kernel<<<BB * HH * (SS / 8), blk>>>(qkv, ctx);
    // 4. output projection
    sgemm_kernel<128, 0><<<dim3(MM / TM, DD / 128), blk>>>(ctx, out_proj_w, out_proj_b, att, DD, DD);
    // 5. add + LN1
    add_ln_kernel<<<MM, blk>>>(x, att, ln1_w, ln1_b, h1);
    // 6. ffn1 + relu
    sgemm_kernel<128, 2><<<dim3(MM / TM, FFN / 128), blk>>>(h1, lin1_w, lin1_b, ff, DD, FFN);
    // 7. ffn2
    sgemm_kernel<128, 0><<<dim3(MM / TM, DD / 128), blk>>>(ff, lin2_w, lin2_b, ff2, FFN, DD);
    // 8. add + LN2
    add_ln_kernel<<<MM, blk>>>(h1, ff2, ln2_w, ln2_b, h2);
    // 9. fc1 (N = 64)
    sgemm_kernel<64, 0><<<dim3(MM / TM, 64 / 64), blk>>>(h2, fc1_w, fc1_b, t64, DD, 64);
    // 10. fc2 head -> logits [B,S]
    fc2_kernel<<<(MM * 32 + 255) / 256, blk>>>(t64, fc2_w, fc2_b, out);
}

// round 2
// speedup vs baseline: 1.0395x; 1.0395x over previous
#include <cuda_runtime.h>
#include <math.h>

#define BB 8
#define SS 2000
#define MM (BB*SS)          // 16000 rows
#define DD 256
#define HH 2
#define HDIM 128
#define FFN 256
#define WIN 99

// ---------------- scratch (device globals; no allocation allowed) ----------
__device__ float g_x   [MM*DD];   // encoder out + pos
__device__ float g_qkv [MM*3*DD]; // packed qkv
__device__ float g_ctx [MM*DD];   // attention context
__device__ float g_att [MM*DD];   // out_proj output
__device__ float g_h1  [MM*DD];   // after LN1
__device__ float g_ff  [MM*FFN];  // relu(ffn1)
__device__ float g_ff2 [MM*DD];   // ffn2
__device__ float g_h2  [MM*DD];   // after LN2
__device__ float g_wc  [260];     // fused head weights (256) + bias (1)

// ---------------- fp32 GEMM, double-buffered ------------------------------
// C[m,n] = sum_k A[m,k]*B[n,k] + bias[n]
// A: [M,K] row-major, B: [N,K] row-major (torch Linear weight layout).
// 128x128 tile, TK=16, 256 threads, 8x8 micro-tile, register-staged loads,
// double-buffered smem, one __syncthreads per K-tile.
// EPI: 0 = bias, 1 = bias + positional encoding, 2 = bias + relu.
#define TM 128
#define TK 16

template<int TN, int EPI, int K>
__global__ void __launch_bounds__(256, 2)
sgemm_kernel(const float* __restrict__ A, const float* __restrict__ B,
             const float* __restrict__ bias, float* __restrict__ C, int N)
{
    constexpr int NT = K / TK;
    __shared__ float As[2][TK][TM + 4];
    __shared__ float Bs[2][TK][TN + 4];

    const int tid  = threadIdx.x;
    const int tx   = tid & 15;         // 0..15 (cols)
    const int ty   = tid >> 4;         // 0..15 (rows)
    const int row0 = blockIdx.x * TM;
    const int col0 = blockIdx.y * TN;
    const int lr   = tid >> 2;         // 0..63
    const int lk   = (tid & 3) * 4;    // 0,4,8,12

    const float* Ap0 = A + (size_t)(row0 + lr) * K + lk;
    const float* Ap1 = Ap0 + (size_t)64 * K;
    const float* Bp0 = B + (size_t)(col0 + lr) * K + lk;
    const float* Bp1 = Bp0 + (size_t)64 * K;

    float acc[8][8];
#pragma unroll
    for (int i = 0; i < 8; i++)
#pragma unroll
        for (int j = 0; j < 8; j++) acc[i][j] = 0.f;

    // prologue: tile 0 -> regs -> smem buf 0
    float4 ra0 = *(const float4*)Ap0;
    float4 ra1 = *(const float4*)Ap1;
    float4 rb0 = *(const float4*)Bp0;
    float4 rb1 = *(const float4*)Bp1;

    As[0][lk+0][lr] = ra0.x; As[0][lk+1][lr] = ra0.y;
    As[0][lk+2][lr] = ra0.z; As[0][lk+3][lr] = ra0.w;
    As[0][lk+0][lr+64] = ra1.x; As[0][lk+1][lr+64] = ra1.y;
    As[0][lk+2][lr+64] = ra1.z; As[0][lk+3][lr+64] = ra1.w;
    Bs[0][lk+0][lr] = rb0.x; Bs[0][lk+1][lr] = rb0.y;
    Bs[0][lk+2][lr] = rb0.z; Bs[0][lk+3][lr] = rb0.w;
    Bs[0][lk+0][lr+64] = rb1.x; Bs[0][lk+1][lr+64] = rb1.y;
    Bs[0][lk+2][lr+64] = rb1.z; Bs[0][lk+3][lr+64] = rb1.w;
    __syncthreads();

    int buf = 0;
#pragma unroll 1
    for (int t = 0; t < NT; t++) {
        // prefetch next tile into registers (overlaps with compute below)
        if (t + 1 < NT) {
            const int off = (t + 1) * TK;
            ra0 = *(const float4*)(Ap0 + off);
            ra1 = *(const float4*)(Ap1 + off);
            rb0 = *(const float4*)(Bp0 + off);
            rb1 = *(const float4*)(Bp1 + off);
        }

        const float (*Ac)[TM + 4] = As[buf];
        const float (*Bc)[TN + 4] = Bs[buf];
#pragma unroll
        for (int k = 0; k < TK; k++) {
            float a[8], b[8];
            *(float4*)&a[0] = *(const float4*)&Ac[k][ty * 8];
            *(float4*)&a[4] = *(const float4*)&Ac[k][ty * 8 + 4];
            *(float4*)&b[0] = *(const float4*)&Bc[k][tx * 8];
            *(float4*)&b[4] = *(const float4*)&Bc[k][tx * 8 + 4];
#pragma unroll
            for (int i = 0; i < 8; i++)
#pragma unroll
                for (int j = 0; j < 8; j++)
                    acc[i][j] += a[i] * b[j];
        }

        if (t + 1 < NT) {
            const int nb = buf ^ 1;
            As[nb][lk+0][lr] = ra0.x; As[nb][lk+1][lr] = ra0.y;
            As[nb][lk+2][lr] = ra0.z; As[nb][lk+3][lr] = ra0.w;
            As[nb][lk+0][lr+64] = ra1.x; As[nb][lk+1][lr+64] = ra1.y;
            As[nb][lk+2][lr+64] = ra1.z; As[nb][lk+3][lr+64] = ra1.w;
            Bs[nb][lk+0][lr] = rb0.x; Bs[nb][lk+1][lr] = rb0.y;
            Bs[nb][lk+2][lr] = rb0.z; Bs[nb][lk+3][lr] = rb0.w;
            Bs[nb][lk+0][lr+64] = rb1.x; Bs[nb][lk+1][lr+64] = rb1.y;
            Bs[nb][lk+2][lr+64] = rb1.z; Bs[nb][lk+3][lr+64] = rb1.w;
            __syncthreads();
            buf = nb;
        }
    }

    // epilogue
#pragma unroll
    for (int i = 0; i < 8; i++) {
        const int r = row0 + ty * 8 + i;
#pragma unroll
        for (int j = 0; j < 8; j++) {
            const int c = col0 + tx * 8 + j;
            float v = acc[i][j] + bias[c];
            if (EPI == 2) v = fmaxf(v, 0.f);
            if (EPI == 1) {
                const int s = r % SS;
                const int p = c >> 1;
                const float div = expf(-(float)(2 * p) * 0.03597789207803197f);
                const float ang = (float)s * div;
                v += (c & 1) ? cosf(ang) : sinf(ang);
            }
            C[(size_t)r * N + c] = v;
        }
    }
}

// ---------------- banded attention: warp per query --------------------------
__global__ void __launch_bounds__(256)
attn_kernel(const float* __restrict__ qkv, float* __restrict__ ctx)
{
    const int w    = threadIdx.x >> 5;
    const int lane = threadIdx.x & 31;
    const int qb   = blockIdx.x;            // 0 .. B*H*(S/8)-1
    const int bh   = qb / (SS / 8);
    const int i    = (qb % (SS / 8)) * 8 + w;
    const int b    = bh >> 1;
    const int h    = bh & 1;

    const float* base = qkv + (size_t)b * SS * (3 * DD);
    const float4 qv = ((const float4*)(base + (size_t)i * (3 * DD) + h * HDIM))[lane];

    const int jstart = (i > WIN) ? (i - WIN) : 0;
    const int cnt    = i - jstart + 1;      // <= 100

    __shared__ float sc[8][104];

    // pass 1: scores + running max
    float mx = -1e30f;
    const float* krow = base + (size_t)jstart * (3 * DD) + DD + h * HDIM;
    for (int jj = 0; jj < cnt; jj++) {
        float4 kv = ((const float4*)(krow + (size_t)jj * (3 * DD)))[lane];
        float p = qv.x * kv.x + qv.y * kv.y + qv.z * kv.z + qv.w * kv.w;
#pragma unroll
        for (int o = 16; o; o >>= 1) p += __shfl_xor_sync(0xffffffffu, p, o);
        p *= 0.08838834764831845f;           // 1/sqrt(128)
        mx = fmaxf(mx, p);
        if (lane == 0) sc[w][jj] = p;
    }
    __syncwarp();

    // pass 2: exp + sum
    float se = 0.f;
    for (int jj = lane; jj < cnt; jj += 32) {
        float e = expf(sc[w][jj] - mx);
        sc[w][jj] = e;
        se += e;
    }
    __syncwarp();
#pragma unroll
    for (int o = 16; o; o >>= 1) se += __shfl_xor_sync(0xffffffffu, se, o);

    // pass 3: weighted V accumulation
    float4 acc = make_float4(0.f, 0.f, 0.f, 0.f);
    const float* vrow = base + (size_t)jstart * (3 * DD) + 2 * DD + h * HDIM;
    for (int jj = 0; jj < cnt; jj++) {
        const float p = sc[w][jj];
        float4 vv = ((const float4*)(vrow + (size_t)jj * (3 * DD)))[lane];
        acc.x += p * vv.x; acc.y += p * vv.y;
        acc.z += p * vv.z; acc.w += p * vv.w;
    }
    const float inv = 1.f / se;
    ((float4*)(ctx + ((size_t)(b * SS + i)) * DD + h * HDIM))[lane] =
        make_float4(acc.x * inv, acc.y * inv, acc.z * inv, acc.w * inv);
}

// ---------------- residual add + layernorm (row per block, single sync) ----
__global__ void __launch_bounds__(256)
add_ln_kernel(const float* __restrict__ x, const float* __restrict__ y,
              const float* __restrict__ w, const float* __restrict__ b,
              float* __restrict__ out)
{
    const int row = blockIdx.x;
    const int t   = threadIdx.x;
    const size_t idx = (size_t)row * DD + t;
    const float v = x[idx] + y[idx];

    __shared__ float s1[8], s2[8];
    float r = v, q = v * v;
#pragma unroll
    for (int o = 16; o; o >>= 1) {
        r += __shfl_xor_sync(0xffffffffu, r, o);
        q += __shfl_xor_sync(0xffffffffu, q, o);
    }
    if ((t & 31) == 0) { s1[t >> 5] = r; s2[t >> 5] = q; }
    __syncthreads();
    float tot  = s1[0]+s1[1]+s1[2]+s1[3]+s1[4]+s1[5]+s1[6]+s1[7];
    float tot2 = s2[0]+s2[1]+s2[2]+s2[3]+s2[4]+s2[5]+s2[6]+s2[7];
    const float mean = tot * (1.f / DD);
    const float var  = tot2 * (1.f / DD) - mean * mean;
    const float inv  = rsqrtf(var + 1e-5f);

    out[idx] = (v - mean) * inv * w[t] + b[t];
}

// ---------------- fused output head --------------------------------------
// logits = h2 @ (fc2_w @ fc1_w).T + (fc2_w @ fc1_b + fc2_b)
__global__ void head_prep_kernel(const float* __restrict__ fc1_w,
                                 const float* __restrict__ fc1_b,
                                 const float* __restrict__ fc2_w,
                                 const float* __restrict__ fc2_b,
                                 float* __restrict__ wc)
{
    const int d = threadIdx.x;   // 256 threads
    float s = 0.f;
#pragma unroll
    for (int j = 0; j < 64; j++) s += fc2_w[j] * fc1_w[j * DD + d];
    wc[d] = s;
    if (d == 0) {
        float bb = fc2_b[0];
        for (int j = 0; j < 64; j++) bb += fc2_w[j] * fc1_b[j];
        wc[256] = bb;
    }
}

__global__ void __launch_bounds__(256)
head_gemv_kernel(const float* __restrict__ h2, const float* __restrict__ wc,
                 float* __restrict__ out)
{
    const int warp = (blockIdx.x * blockDim.x + threadIdx.x) >> 5;
    const int lane = threadIdx.x & 31;
    if (warp >= MM) return;
    const float* r = h2 + (size_t)warp * DD;
    float s = 0.f;
#pragma unroll
    for (int c = 0; c < 8; c++) s += r[lane + 32 * c] * wc[lane + 32 * c];
#pragma unroll
    for (int o = 16; o; o >>= 1) s += __shfl_xor_sync(0xffffffffu, s, o);
    if (lane == 0) out[warp] = s + wc[256];
}

// ---------------- host launch ------------------------------------------------
static float* dptr(const void* sym) {
    void* p = nullptr;
    cudaGetSymbolAddress(&p, sym);
    return (float*)p;
}

extern "C" void kernel_launch(void* const* d_in, const int* in_sizes, int n_in,
                              void* d_out, int out_size)
{
    const float* src        = (const float*)d_in[0];
    // d_in[1] = input_lengths (int64) — unused by the reference math
    const float* W_enc      = (const float*)d_in[2];
    const float* b_enc      = (const float*)d_in[3];
    const float* in_proj_w  = (const float*)d_in[4];
    const float* in_proj_b  = (const float*)d_in[5];
    const float* out_proj_w = (const float*)d_in[6];
    const float* out_proj_b = (const float*)d_in[7];
    const float* ln1_w      = (const float*)d_in[8];
    const float* ln1_b      = (const float*)d_in[9];
    const float* lin1_w     = (const float*)d_in[10];
    const float* lin1_b     = (const float*)d_in[11];
    const float* lin2_w     = (const float*)d_in[12];
    const float* lin2_b     = (const float*)d_in[13];
    const float* ln2_w      = (const float*)d_in[14];
    const float* ln2_b      = (const float*)d_in[15];
    const float* fc1_w      = (const float*)d_in[16];
    const float* fc1_b      = (const float*)d_in[17];
    const float* fc2_w      = (const float*)d_in[18];
    const float* fc2_b      = (const float*)d_in[19];
    float* out = (float*)d_out;

    float* x   = dptr(g_x);
    float* qkv = dptr(g_qkv);
    float* ctx = dptr(g_ctx);
    float* att = dptr(g_att);
    float* h1  = dptr(g_h1);
    float* ff  = dptr(g_ff);
    float* ff2 = dptr(g_ff2);
    float* h2  = dptr(g_h2);
    float* wc  = dptr(g_wc);

    const dim3 blk(256);

    // head prep (tiny, independent — run first)
    head_prep_kernel<<<1, 256>>>(fc1_w, fc1_b, fc2_w, fc2_b, wc);

    // 1. encoder projection + positional encoding
    sgemm_kernel<128, 1, DD><<<dim3(MM / TM, DD / 128), blk>>>(src, W_enc, b_enc, x, DD);
    // 2. qkv projection
    sgemm_kernel<128, 0, DD><<<dim3(MM / TM, (3 * DD) / 128), blk>>>(x, in_proj_w, in_proj_b, qkv, 3 * DD);
    // 3. banded attention
    attn_kernel<<<BB * HH * (SS / 8), blk>>>(qkv, ctx);
    // 4. output projection
    sgemm_kernel<128, 0, DD><<<dim3(MM / TM, DD / 128), blk>>>(ctx, out_proj_w, out_proj_b, att, DD);
    // 5. add + LN1
    add_ln_kernel<<<MM, blk>>>(x, att, ln1_w, ln1_b, h1);
    // 6. ffn1 + relu
    sgemm_kernel<128, 2, DD><<<dim3(MM / TM, FFN / 128), blk>>>(h1, lin1_w, lin1_b, ff, FFN);
    // 7. ffn2
    sgemm_kernel<128, 0, FFN><<<dim3(MM / TM, DD / 128), blk>>>(ff, lin2_w, lin2_b, ff2, DD);
    // 8. add + LN2
    add_ln_kernel<<<MM, blk>>>(h1, ff2, ln2_w, ln2_b, h2);
    // 9. fused head -> logits [B,S]
    head_gemv_kernel<<<(MM * 32 + 255) / 256, blk>>>(h2, wc, out);
}